// round 2
// baseline (speedup 1.0000x reference)
#include <cuda_runtime.h>

#define BATCH 16
#define DIM   512
#define S     128
#define IMG   (S*S)          // 16384 floats per (b,c) plane
#define IMG4  (IMG/4)        // 4096 float4 per plane

// scratch: x2[b, o(2), h, w]  (2 MB) — device global, no allocation
__device__ float g_x2[BATCH * 2 * IMG];

// ---------------------------------------------------------------------------
// Kernel 1: 1x1 conv channel reduction  x[B,512,S,S] -> x2[B,2,S,S]
// One thread per float4 along W. 65536 threads total.
// ---------------------------------------------------------------------------
__global__ __launch_bounds__(256) void swa_k1(const float* __restrict__ x,
                                              const float* __restrict__ w_conv) {
    __shared__ float w0[DIM];
    __shared__ float w1[DIM];
    for (int i = threadIdx.x; i < DIM; i += blockDim.x) {
        w0[i] = w_conv[i];          // o=0
        w1[i] = w_conv[DIM + i];    // o=1
    }
    __syncthreads();

    int tid = blockIdx.x * blockDim.x + threadIdx.x;   // 0..65535
    int b   = tid >> 12;                               // / IMG4
    int p   = tid & (IMG4 - 1);                        // float4 index in plane

    const float4* base = reinterpret_cast<const float4*>(x)
                       + (size_t)b * DIM * IMG4 + p;

    float4 a0 = make_float4(0.f, 0.f, 0.f, 0.f);
    float4 a1 = make_float4(0.f, 0.f, 0.f, 0.f);

#pragma unroll 8
    for (int c = 0; c < DIM; c++) {
        float4 v = __ldcs(base + (size_t)c * IMG4);    // streaming: no reuse
        float f0 = w0[c];
        float f1 = w1[c];
        a0.x = fmaf(f0, v.x, a0.x);  a0.y = fmaf(f0, v.y, a0.y);
        a0.z = fmaf(f0, v.z, a0.z);  a0.w = fmaf(f0, v.w, a0.w);
        a1.x = fmaf(f1, v.x, a1.x);  a1.y = fmaf(f1, v.y, a1.y);
        a1.z = fmaf(f1, v.z, a1.z);  a1.w = fmaf(f1, v.w, a1.w);
    }

    float4* out = reinterpret_cast<float4*>(g_x2) + (size_t)b * 2 * IMG4 + p;
    out[0]    = a0;   // o = 0 plane
    out[IMG4] = a1;   // o = 1 plane
}

// ---------------------------------------------------------------------------
// Kernel 2: strip convs + linear + sigmoid + outer product, one block / batch
//   ww_raw[b,wo] = sum_{c,h,kw} x2[b,c,h,wo-2+kw] * w_ww[c,h,kw]   (pad 0,2)
//   hw_raw[b,ho] = sum_{c,kh,w} x2[b,c,ho-2+kh,w] * w_hw[c,kh,w]   (pad 2,0)
//   ww = sigmoid(ww_raw @ W_ww^T + b_ww);  hw likewise
//   out[b,h,w] = hw[h] * ww[w]
// ---------------------------------------------------------------------------
__global__ __launch_bounds__(128) void swa_k2(const float* __restrict__ w_ww,   // [2,128,5]
                                              const float* __restrict__ w_hw,   // [2,5,128]
                                              const float* __restrict__ ww_lw,  // [128,128]
                                              const float* __restrict__ ww_lb,  // [128]
                                              const float* __restrict__ hw_lw,  // [128,128]
                                              const float* __restrict__ hw_lb,  // [128]
                                              float* __restrict__ out) {
    const int b = blockIdx.x;
    const int t = threadIdx.x;  // 0..127

    __shared__ float s_ww_raw[S];
    __shared__ float s_hw_raw[S];
    __shared__ float s_ww[S];
    __shared__ float s_hw[S];

    const float* x2 = g_x2 + (size_t)b * 2 * IMG;

    // --- ww branch raw conv: output index = t (along W) ---
    float acc_w = 0.f;
    for (int c = 0; c < 2; c++) {
        const float* plane = x2 + c * IMG;
        const float* wgt   = w_ww + c * (S * 5);
        for (int h = 0; h < S; h++) {
            const float* row = plane + h * S;
            const float* wr  = wgt + h * 5;
#pragma unroll
            for (int kw = 0; kw < 5; kw++) {
                int wi = t - 2 + kw;
                if (wi >= 0 && wi < S)
                    acc_w = fmaf(row[wi], wr[kw], acc_w);
            }
        }
    }
    s_ww_raw[t] = acc_w;

    // --- hw branch raw conv: output index = t (along H) ---
    float acc_h = 0.f;
    for (int c = 0; c < 2; c++) {
        const float* plane = x2 + c * IMG;
        const float* wgt   = w_hw + c * (5 * S);
#pragma unroll
        for (int kh = 0; kh < 5; kh++) {
            int hi = t - 2 + kh;
            if (hi < 0 || hi >= S) continue;
            const float* row = plane + hi * S;
            const float* wr  = wgt + kh * S;
#pragma unroll 4
            for (int w = 0; w < S; w++)
                acc_h = fmaf(row[w], wr[w], acc_h);
        }
    }
    s_hw_raw[t] = acc_h;
    __syncthreads();

    // --- linear + sigmoid (row t of each weight matrix) ---
    float sw = ww_lb[t];
    float sh = hw_lb[t];
    const float* wwr = ww_lw + t * S;
    const float* hwr = hw_lw + t * S;
#pragma unroll 4
    for (int k = 0; k < S; k++) {
        sw = fmaf(s_ww_raw[k], wwr[k], sw);
        sh = fmaf(s_hw_raw[k], hwr[k], sh);
    }
    s_ww[t] = 1.f / (1.f + expf(-sw));
    s_hw[t] = 1.f / (1.f + expf(-sh));
    __syncthreads();

    // --- outer product store: out[b, h, w] = s_hw[h] * s_ww[w] ---
    float4* o = reinterpret_cast<float4*>(out + (size_t)b * IMG);
    const float4* wwv = reinterpret_cast<const float4*>(s_ww);
#pragma unroll 4
    for (int i = t; i < IMG4; i += 128) {
        int h  = i >> 5;          // /32 float4 per row
        int w4 = i & 31;
        float hv = s_hw[h];
        float4 wv = wwv[w4];
        o[i] = make_float4(hv * wv.x, hv * wv.y, hv * wv.z, hv * wv.w);
    }
}

// ---------------------------------------------------------------------------
extern "C" void kernel_launch(void* const* d_in, const int* in_sizes, int n_in,
                              void* d_out, int out_size) {
    const float* x      = (const float*)d_in[0];
    const float* w_conv = (const float*)d_in[1];
    const float* w_ww   = (const float*)d_in[2];
    const float* w_hw   = (const float*)d_in[3];
    const float* ww_lw  = (const float*)d_in[4];
    const float* ww_lb  = (const float*)d_in[5];
    const float* hw_lw  = (const float*)d_in[6];
    const float* hw_lb  = (const float*)d_in[7];
    float* out = (float*)d_out;

    // k1: 65536 threads (one per float4 of the 16 output planes)
    swa_k1<<<(BATCH * IMG4) / 256, 256>>>(x, w_conv);
    // k2: one block per batch
    swa_k2<<<BATCH, 128>>>(w_ww, w_hw, ww_lw, ww_lb, hw_lw, hw_lb, out);
}

// round 4
// speedup vs baseline: 2.2248x; 2.2248x over previous
#include <cuda_runtime.h>

#define BATCH 16
#define DIM   512
#define S     128
#define IMG   (S*S)          // 16384 floats per (b,c) plane
#define IMG4  (IMG/4)
#define CS    2              // channel splits in k1
#define CPS   (DIM/CS)       // channels per split (256)

// partial channel-reduced planes: [split][b][o(2)][h][w]  (4 MB, L2-resident)
__device__ float g_x2p[CS * BATCH * 2 * IMG];
// raw strip-conv outputs: [branch(2)][b][128]
__device__ float g_raw[2 * BATCH * S];

// ---------------------------------------------------------------------------
// k1: 1x1 conv channel reduction, 2-way channel split for MLP + wave balance.
// 131072 threads, each owns one float4 along W for half the channels.
// ---------------------------------------------------------------------------
__global__ __launch_bounds__(128) void swa_k1(const float* __restrict__ x,
                                              const float* __restrict__ w_conv) {
    __shared__ float w0[DIM];
    __shared__ float w1[DIM];
    for (int i = threadIdx.x; i < DIM; i += blockDim.x) {
        w0[i] = w_conv[i];          // o=0
        w1[i] = w_conv[DIM + i];    // o=1
    }
    __syncthreads();

    int tid  = blockIdx.x * blockDim.x + threadIdx.x;  // 0..131071
    int half = tid >> 16;                              // channel split
    int rem  = tid & 65535;
    int b    = rem >> 12;
    int p    = rem & (IMG4 - 1);

    const float4* base = reinterpret_cast<const float4*>(x)
                       + (size_t)b * DIM * IMG4 + (size_t)half * CPS * IMG4 + p;
    const int cbase = half * CPS;

    float4 a0 = make_float4(0.f, 0.f, 0.f, 0.f);
    float4 a1 = make_float4(0.f, 0.f, 0.f, 0.f);

#pragma unroll 8
    for (int c = 0; c < CPS; c++) {
        float4 v = __ldcs(base + (size_t)c * IMG4);    // streaming, no reuse
        float f0 = w0[cbase + c];
        float f1 = w1[cbase + c];
        a0.x = fmaf(f0, v.x, a0.x);  a0.y = fmaf(f0, v.y, a0.y);
        a0.z = fmaf(f0, v.z, a0.z);  a0.w = fmaf(f0, v.w, a0.w);
        a1.x = fmaf(f1, v.x, a1.x);  a1.y = fmaf(f1, v.y, a1.y);
        a1.z = fmaf(f1, v.z, a1.z);  a1.w = fmaf(f1, v.w, a1.w);
    }

    float4* out = reinterpret_cast<float4*>(g_x2p)
                + (size_t)half * (BATCH * 2 * IMG4)
                + (size_t)b * 2 * IMG4 + p;
    out[0]    = a0;
    out[IMG4] = a1;
}

// ---------------------------------------------------------------------------
// k2a: strip convs via one warp per output. 4096 warps = 512 blocks x 256.
//   branch 0 (ww): raw[wo] = sum_{c,h,kw} x2[b,c,h,wo-2+kw] * w_ww[c,h,kw]
//   branch 1 (hw): raw[ho] = sum_{c,kh,w} x2[b,c,ho-2+kh,w] * w_hw[c,kh,w]
// x2 reconstructed as sum of the two k1 partials (both L2-hot).
// ---------------------------------------------------------------------------
__global__ __launch_bounds__(256) void swa_k2a(const float* __restrict__ w_ww,
                                               const float* __restrict__ w_hw) {
    int gw   = (blockIdx.x * 256 + threadIdx.x) >> 5;  // global warp 0..4095
    int lane = threadIdx.x & 31;
    int b      = gw >> 8;
    int r      = gw & 255;
    int branch = r >> 7;
    int o      = r & 127;

    const float* p0 = g_x2p + (size_t)b * 2 * IMG;
    const float* p1 = p0 + (size_t)(BATCH * 2 * IMG);

    float acc = 0.f;
    if (branch == 0) {
        // 1280 terms: idx = (c*128 + h)*5 + kw
        for (int idx = lane; idx < 2 * S * 5; idx += 32) {
            int c  = idx / (S * 5);
            int r2 = idx - c * (S * 5);
            int h  = r2 / 5;
            int kw = r2 - h * 5;
            int wi = o - 2 + kw;
            if (wi >= 0 && wi < S) {
                int off = c * IMG + h * S + wi;
                acc = fmaf(p0[off] + p1[off], w_ww[idx], acc);
            }
        }
    } else {
        // 1280 terms: idx = (c*5 + kh)*128 + w
        for (int idx = lane; idx < 2 * 5 * S; idx += 32) {
            int c  = idx / (5 * S);
            int r2 = idx - c * (5 * S);
            int kh = r2 >> 7;
            int w  = r2 & 127;
            int hi = o - 2 + kh;
            if (hi >= 0 && hi < S) {
                int off = c * IMG + hi * S + w;
                acc = fmaf(p0[off] + p1[off], w_hw[idx], acc);
            }
        }
    }
#pragma unroll
    for (int sft = 16; sft; sft >>= 1)
        acc += __shfl_xor_sync(0xFFFFFFFFu, acc, sft);
    if (lane == 0)
        g_raw[branch * (BATCH * S) + b * S + o] = acc;
}

// ---------------------------------------------------------------------------
// k2b: linear + sigmoid + outer product. One block (256 thr) per batch.
// ---------------------------------------------------------------------------
__global__ __launch_bounds__(256) void swa_k2b(const float* __restrict__ ww_lw,
                                               const float* __restrict__ ww_lb,
                                               const float* __restrict__ hw_lw,
                                               const float* __restrict__ hw_lb,
                                               float* __restrict__ out) {
    const int b = blockIdx.x;
    const int t = threadIdx.x;

    __shared__ float s_wwraw[S];
    __shared__ float s_hwraw[S];
    __shared__ float s_ww[S];
    __shared__ float s_hw[S];

    if (t < S) {
        s_wwraw[t] = g_raw[b * S + t];
        s_hwraw[t] = g_raw[BATCH * S + b * S + t];
    }
    __syncthreads();

    if (t < S) {
        float sw = ww_lb[t];
        float sh = hw_lb[t];
        const float* wwr = ww_lw + t * S;
        const float* hwr = hw_lw + t * S;
#pragma unroll 4
        for (int k = 0; k < S; k++) {
            sw = fmaf(s_wwraw[k], wwr[k], sw);
            sh = fmaf(s_hwraw[k], hwr[k], sh);
        }
        s_ww[t] = 1.f / (1.f + expf(-sw));
        s_hw[t] = 1.f / (1.f + expf(-sh));
    }
    __syncthreads();

    float4* o = reinterpret_cast<float4*>(out + (size_t)b * IMG);
    const float4* wwv = reinterpret_cast<const float4*>(s_ww);
#pragma unroll 4
    for (int i = t; i < IMG4; i += 256) {
        int h  = i >> 5;
        int w4 = i & 31;
        float hv  = s_hw[h];
        float4 wv = wwv[w4];
        o[i] = make_float4(hv * wv.x, hv * wv.y, hv * wv.z, hv * wv.w);
    }
}

// ---------------------------------------------------------------------------
extern "C" void kernel_launch(void* const* d_in, const int* in_sizes, int n_in,
                              void* d_out, int out_size) {
    const float* x      = (const float*)d_in[0];
    const float* w_conv = (const float*)d_in[1];
    const float* w_ww   = (const float*)d_in[2];
    const float* w_hw   = (const float*)d_in[3];
    const float* ww_lw  = (const float*)d_in[4];
    const float* ww_lb  = (const float*)d_in[5];
    const float* hw_lw  = (const float*)d_in[6];
    const float* hw_lb  = (const float*)d_in[7];
    float* out = (float*)d_out;

    swa_k1<<<(CS * BATCH * IMG4) / 128, 128>>>(x, w_conv);
    swa_k2a<<<(BATCH * 2 * S * 32) / 256, 256>>>(w_ww, w_hw);
    swa_k2b<<<BATCH, 256>>>(ww_lw, ww_lb, hw_lw, hw_lb, out);
}